// round 5
// baseline (speedup 1.0000x reference)
#include <cuda_runtime.h>
#include <cuda_bf16.h>

#define GS 32
#define NN 16
#define SLICES 4
#define ATOM_TYPE 6
#define MAX_BA 256   // supports B <= 8

// Scratch: compacted separable factor tables per (ba, m):
// layout [ba][m][dim][32] floats, dim 0=ex(i), 1=ey(j), 2=ez(k).
__device__ float g_tab[MAX_BA * NN * 3 * GS];
__device__ int   g_nact[MAX_BA];

// ---------------- Kernel A: per-ba factor tables (tiny) ----------------
// One block per ba, 96 threads = 3 warps. Warp w handles dim w; lane = grid idx.
__global__ __launch_bounds__(96) void precompute_kernel(
    const float* __restrict__ dv,     // (B, A, N, 3)
    const int*   __restrict__ an,     // (A, N) int32
    const float* __restrict__ sigma)  // (1,)
{
    const int ba   = blockIdx.x;
    const int a    = ba & 31;
    const int dim  = threadIdx.x >> 5;   // 0..2
    const int lane = threadIdx.x & 31;   // grid position g

    // Each warp does its own ballot (an[] is a tiny broadcast load, no barrier).
    bool act = (lane < NN) && (an[a * NN + lane] == ATOM_TYPE);
    unsigned mask = __ballot_sync(0xffffffffu, act);
    if (threadIdx.x == 0) g_nact[ba] = __popc(mask);

    const float sg = __ldg(sigma);
    const float coeff = -0.5f / (sg * sg);
    const float step = 8.0f / 31.0f;
    const float tick = -4.0f + (float)lane * step;

    int m = 0;
    while (mask) {
        const int n = __ffs(mask) - 1;
        mask &= mask - 1;
        const float d = dv[((long)ba * NN + n) * 3 + dim];
        const float dd = tick - d;
        g_tab[((ba * NN + m) * 3 + dim) * GS + lane] = __expf(coeff * dd * dd);
        ++m;
    }
}

// ---------------- Kernel B: pure streaming accumulate ----------------
// Block = (ba, iq of 4 i-slices), 256 threads. Thread t: j = t>>3, k0 = (t&7)*4.
// Per active neighbor: 3 cached LDGs + 4 MUL + 16 FMA. No barriers, no MUFU.
__global__ __launch_bounds__(256) void accum_kernel(
    float* __restrict__ out)          // (B, A, G, G, G)
{
    const int ba = blockIdx.x;
    const int iq = blockIdx.y;        // slices [iq*4, iq*4+4)
    const int t  = threadIdx.x;
    const int j  = t >> 3;
    const int k0 = (t & 7) << 2;

    const int nact = g_nact[ba];
    const float* base = g_tab + (long)ba * (NN * 3 * GS);

    float4 acc[SLICES];
    #pragma unroll
    for (int ii = 0; ii < SLICES; ++ii) acc[ii] = make_float4(0.f, 0.f, 0.f, 0.f);

    for (int m = 0; m < nact; ++m) {
        const float* row = base + m * (3 * GS);
        const float4 ex4 = __ldg(reinterpret_cast<const float4*>(row + iq * SLICES));
        const float  eyj = __ldg(row + GS + j);
        float4 ez4 = __ldg(reinterpret_cast<const float4*>(row + 2 * GS + k0));
        ez4.x *= eyj; ez4.y *= eyj; ez4.z *= eyj; ez4.w *= eyj;

        acc[0].x = fmaf(ex4.x, ez4.x, acc[0].x);
        acc[0].y = fmaf(ex4.x, ez4.y, acc[0].y);
        acc[0].z = fmaf(ex4.x, ez4.z, acc[0].z);
        acc[0].w = fmaf(ex4.x, ez4.w, acc[0].w);
        acc[1].x = fmaf(ex4.y, ez4.x, acc[1].x);
        acc[1].y = fmaf(ex4.y, ez4.y, acc[1].y);
        acc[1].z = fmaf(ex4.y, ez4.z, acc[1].z);
        acc[1].w = fmaf(ex4.y, ez4.w, acc[1].w);
        acc[2].x = fmaf(ex4.z, ez4.x, acc[2].x);
        acc[2].y = fmaf(ex4.z, ez4.y, acc[2].y);
        acc[2].z = fmaf(ex4.z, ez4.z, acc[2].z);
        acc[2].w = fmaf(ex4.z, ez4.w, acc[2].w);
        acc[3].x = fmaf(ex4.w, ez4.x, acc[3].x);
        acc[3].y = fmaf(ex4.w, ez4.y, acc[3].y);
        acc[3].z = fmaf(ex4.w, ez4.z, acc[3].z);
        acc[3].w = fmaf(ex4.w, ez4.w, acc[3].w);
    }

    float* outp = out + (long)ba * (GS * GS * GS)
                      + (long)(iq * SLICES) * (GS * GS)
                      + 4 * t;   // j*32 + k0 == 4*t
    #pragma unroll
    for (int ii = 0; ii < SLICES; ++ii)
        *reinterpret_cast<float4*>(outp + ii * (GS * GS)) = acc[ii];
}

extern "C" void kernel_launch(void* const* d_in, const int* in_sizes, int n_in,
                              void* d_out, int out_size) {
    const float* dv    = (const float*)d_in[0];   // distance_vector (B,32,16,3)
    const int*   an    = (const int*)d_in[1];     // atomic_numbers (32,16) int32
    const float* sigma = (const float*)d_in[2];   // (1,)
    float* out = (float*)d_out;

    const int B = in_sizes[0] / (32 * 16 * 3);    // derive batch from input size

    precompute_kernel<<<B * 32, 96>>>(dv, an, sigma);
    dim3 grid(B * 32, GS / SLICES);               // (128, 8)
    accum_kernel<<<grid, 256>>>(out);
}

// round 6
// speedup vs baseline: 1.1667x; 1.1667x over previous
#include <cuda_runtime.h>
#include <cuda_bf16.h>

#define GS 32
#define NN 16
#define SLICES 4
#define ATOM_TYPE 6

// out[b,a,i,j,k] = sum_{n: an[a,n]==6} exp(coeff*||grid - dv||^2), separable:
// ex[i]*ey[j]*ez[k]. Block = (ba, group of 4 i-slices), 256 threads.
// Thread t owns (j = t>>3, k0 = (t&7)*4) -> 4 float4 register accumulators.
// __launch_bounds__(256, 8): force <=32 regs so 8 CTAs/SM -> true single wave.
__global__ __launch_bounds__(256, 8) void voxel_kernel(
    const float* __restrict__ dv,     // (B, A, N, 3)
    const int*   __restrict__ an,     // (A, N) int32
    const float* __restrict__ sigma,  // (1,)
    float* __restrict__ out)          // (B, A, G, G, G)
{
    const int ba = blockIdx.x;        // b*32 + a
    const int a  = ba & 31;
    const int iq = blockIdx.y;        // slices [iq*4, iq*4+4)
    const int t  = threadIdx.x;
    const int j  = t >> 3;
    const int k0 = (t & 7) << 2;

    __shared__ float s_ey[NN][GS];
    __shared__ __align__(16) float s_ez[NN][GS];
    __shared__ float s_exi[NN][SLICES];

    // Warm L1 with this block's dv rows, concurrent with the an load below.
    float pf = 0.0f;
    if (t < NN * 3) pf = dv[ba * (NN * 3) + t];
    asm volatile("" :: "f"(pf));

    // Per-warp ballot compaction (warp-uniform mask, no shared, no extra barrier).
    const int lane = t & 31;
    bool act = (lane < NN) && (an[a * NN + lane] == ATOM_TYPE);
    const unsigned mask = __ballot_sync(0xffffffffu, act);
    const int nact = __popc(mask);

    const float sg = __ldg(sigma);
    const float coeff = -0.5f / (sg * sg);
    const float step = 8.0f / 31.0f;

    // Phase B: separable factor tables (compact index m -> neighbor n via __fns).
    for (int idx = t; idx < nact * GS; idx += 256) {        // <= 512 items
        const int m = idx >> 5, g = idx & 31;
        const int n = (int)__fns(mask, 0, m + 1);
        const int rb = (ba * NN + n) * 3;
        const float dy = dv[rb + 1];                        // L1 hit (prefetched)
        const float dz = dv[rb + 2];
        const float tick = -4.0f + (float)g * step;
        const float ddy = tick - dy;
        const float ddz = tick - dz;
        s_ey[m][g] = __expf(coeff * ddy * ddy);
        s_ez[m][g] = __expf(coeff * ddz * ddz);
    }
    if (t < nact * SLICES) {                                 // <= 64 items
        const int m = t >> 2, ii = t & 3;
        const int n = (int)__fns(mask, 0, m + 1);
        const float dx = dv[(ba * NN + n) * 3];
        const float tick = -4.0f + (float)(iq * SLICES + ii) * step;
        const float ddx = tick - dx;
        s_exi[m][ii] = __expf(coeff * ddx * ddx);
    }
    __syncthreads();

    // Accumulate: per m hoist ey[j]*ez4, then 4 slices x 4 FMA.
    float4 acc[SLICES];
    #pragma unroll
    for (int ii = 0; ii < SLICES; ++ii) acc[ii] = make_float4(0.f, 0.f, 0.f, 0.f);

    for (int m = 0; m < nact; ++m) {
        const float eyj = s_ey[m][j];                              // broadcast LDS
        float4 ez4 = *reinterpret_cast<const float4*>(&s_ez[m][k0]);
        ez4.x *= eyj; ez4.y *= eyj; ez4.z *= eyj; ez4.w *= eyj;
        #pragma unroll
        for (int ii = 0; ii < SLICES; ++ii) {
            const float ex = s_exi[m][ii];                         // broadcast LDS
            acc[ii].x = fmaf(ex, ez4.x, acc[ii].x);
            acc[ii].y = fmaf(ex, ez4.y, acc[ii].y);
            acc[ii].z = fmaf(ex, ez4.z, acc[ii].z);
            acc[ii].w = fmaf(ex, ez4.w, acc[ii].w);
        }
    }

    // 32-bit offsets throughout (16M floats < 2^31).
    float* outp = out + ba * (GS * GS * GS)
                      + (iq * SLICES) * (GS * GS)
                      + 4 * t;   // j*32 + k0 == 4*t
    #pragma unroll
    for (int ii = 0; ii < SLICES; ++ii)
        *reinterpret_cast<float4*>(outp + ii * (GS * GS)) = acc[ii];
}

extern "C" void kernel_launch(void* const* d_in, const int* in_sizes, int n_in,
                              void* d_out, int out_size) {
    const float* dv    = (const float*)d_in[0];   // distance_vector (B,32,16,3)
    const int*   an    = (const int*)d_in[1];     // atomic_numbers (32,16) int32
    const float* sigma = (const float*)d_in[2];   // (1,)
    float* out = (float*)d_out;

    const int B = in_sizes[0] / (32 * 16 * 3);    // derive batch from input size
    dim3 grid(B * 32, GS / SLICES);               // (128, 8) = 1024 blocks
    voxel_kernel<<<grid, 256>>>(dv, an, sigma, out);
}

// round 8
// speedup vs baseline: 1.2086x; 1.0360x over previous
#include <cuda_runtime.h>
#include <cuda_bf16.h>

#define GS 32
#define NN 16
#define SLICES 4
#define ATOM_TYPE 6

// Single MUFU EX2 regardless of compile flags.
__device__ __forceinline__ float ex2(float x) {
    float r;
    asm("ex2.approx.ftz.f32 %0, %1;" : "=f"(r) : "f"(x));
    return r;
}

// out[b,a,i,j,k] = sum_{n: an[a,n]==6} exp(c*||grid - dv||^2), c = -0.5/sigma^2.
// Separable Gaussian on a UNIFORM grid => geometric ratio recurrence:
//   e(g+1) = e(g) * r(g),  r(g+1) = r(g) * q,  q = exp2(2*c2*step^2) const.
// Per neighbor each thread seeds 3 ex2 (base, z-ratio, x-ratio) and generates
// all 16 of its outputs with multiplies. Register-only, barrier-free.
// Block = (ba, group of 4 i-slices), 256 threads; thread t: j=t>>3, k0=(t&7)*4.
__global__ __launch_bounds__(256) void voxel_kernel(
    const float* __restrict__ dv,     // (B, A, N, 3)
    const int*   __restrict__ an,     // (A, N) int32
    const float* __restrict__ sigma,  // (1,)
    float* __restrict__ out)          // (B, A, G, G, G)
{
    const int ba = blockIdx.x;        // b*32 + a
    const int a  = ba & 31;
    const int iq = blockIdx.y;        // slices [iq*4, iq*4+4)
    const int t  = threadIdx.x;
    const int j  = t >> 3;
    const int k0 = (t & 7) << 2;
    const int lane = t & 31;

    // sigma heads the dependency chain into every exp -> issue first.
    const float sg = __ldg(sigma);

    // Warm L1 with this block's dv rows, concurrent with the an load.
    float pf = 0.0f;
    if (t < NN * 3) pf = dv[ba * (NN * 3) + t];
    asm volatile("" :: "f"(pf));

    // Per-warp ballot compaction (warp-uniform mask; no shared, no barrier).
    bool act = (lane < NN) && (an[a * NN + lane] == ATOM_TYPE);
    unsigned mask = __ballot_sync(0xffffffffu, act);

    const float step = 8.0f / 31.0f;
    const float c2 = (-0.5f / (sg * sg)) * 1.4426950408889634f;  // coeff * log2(e)
    const float q  = ex2(2.0f * c2 * step * step);               // hoisted constant

    const float ti0 = -4.0f + (float)(iq * SLICES) * step;
    const float tj  = -4.0f + (float)j * step;
    const float tk0 = -4.0f + (float)k0 * step;

    float4 acc[SLICES];
    #pragma unroll
    for (int ii = 0; ii < SLICES; ++ii) acc[ii] = make_float4(0.f, 0.f, 0.f, 0.f);

    while (mask) {
        const int n = __ffs(mask) - 1;
        mask &= mask - 1;

        const float* p = dv + (ba * NN + n) * 3;   // L1 hit (prefetched)
        const float dx = p[0], dy = p[1], dz = p[2];

        const float ddx = ti0 - dx;
        const float ddy = tj  - dy;
        const float ddz = tk0 - dz;

        // Seeds: base value at (i0, j, k0) and first-step ratios along z and x.
        const float argb = c2 * (ddx * ddx + ddy * ddy + ddz * ddz);
        const float e0 = ex2(argb);
        float rz = ex2(c2 * fmaf(2.0f * ddz, step, step * step));
        float rx = ex2(c2 * fmaf(2.0f * ddx, step, step * step));

        // z-row at slice i0 via ratio walk (5 MUL).
        float v0 = e0;
        float v1 = v0 * rz;  rz *= q;
        float v2 = v1 * rz;  rz *= q;
        float v3 = v2 * rz;

        // x multipliers X1..X3 via ratio walk (5 MUL); X0 = 1.
        const float x1 = rx;            rx *= q;
        const float x2 = x1 * rx;       rx *= q;
        const float x3 = x2 * rx;

        acc[0].x += v0;           acc[0].y += v1;
        acc[0].z += v2;           acc[0].w += v3;
        acc[1].x = fmaf(x1, v0, acc[1].x);
        acc[1].y = fmaf(x1, v1, acc[1].y);
        acc[1].z = fmaf(x1, v2, acc[1].z);
        acc[1].w = fmaf(x1, v3, acc[1].w);
        acc[2].x = fmaf(x2, v0, acc[2].x);
        acc[2].y = fmaf(x2, v1, acc[2].y);
        acc[2].z = fmaf(x2, v2, acc[2].z);
        acc[2].w = fmaf(x2, v3, acc[2].w);
        acc[3].x = fmaf(x3, v0, acc[3].x);
        acc[3].y = fmaf(x3, v1, acc[3].y);
        acc[3].z = fmaf(x3, v2, acc[3].z);
        acc[3].w = fmaf(x3, v3, acc[3].w);
    }

    float* outp = out + ba * (GS * GS * GS)
                      + (iq * SLICES) * (GS * GS)
                      + 4 * t;   // j*32 + k0 == 4*t
    #pragma unroll
    for (int ii = 0; ii < SLICES; ++ii)
        *reinterpret_cast<float4*>(outp + ii * (GS * GS)) = acc[ii];
}

extern "C" void kernel_launch(void* const* d_in, const int* in_sizes, int n_in,
                              void* d_out, int out_size) {
    const float* dv    = (const float*)d_in[0];   // distance_vector (B,32,16,3)
    const int*   an    = (const int*)d_in[1];     // atomic_numbers (32,16) int32
    const float* sigma = (const float*)d_in[2];   // (1,)
    float* out = (float*)d_out;

    const int B = in_sizes[0] / (32 * 16 * 3);    // derive batch from input size
    dim3 grid(B * 32, GS / SLICES);               // (128, 8) = 1024 blocks
    voxel_kernel<<<grid, 256>>>(dv, an, sigma, out);
}